// round 1
// baseline (speedup 1.0000x reference)
#include <cuda_runtime.h>
#include <cstdint>

#define D_DIM 128

// ---------------- device scratch (no allocations allowed) ----------------
__device__ double g_dots_acc;
__device__ float  g_M[D_DIM * D_DIM];   // M = U U^T
__device__ float  g_W[D_DIM * D_DIM];   // W = U diag(cnt) U^T
__device__ float  g_cnt[4096];          // histogram of G (P <= 4096)
__device__ int    g_idx64;              // 1 if index arrays are int64, 0 if int32

__device__ __forceinline__ long long ld_idx(const void* p, long long i, int is64) {
    if (is64) return ((const long long*)p)[i];
    return (long long)((const int*)p)[i];
}

// ---------------- kernel Z: zero scratch + detect index dtype ----------------
__global__ void k_init(const void* merge_idx, long long N, int P) {
    long long tid = (long long)blockIdx.x * blockDim.x + threadIdx.x;
    long long stride = (long long)gridDim.x * blockDim.x;
    for (long long i = tid; i < (long long)D_DIM * D_DIM; i += stride) {
        g_M[i] = 0.f;
        g_W[i] = 0.f;
    }
    for (long long i = tid; i < P; i += stride) g_cnt[i] = 0.f;
    if (tid == 0) {
        g_dots_acc = 0.0;
        // Detect int64 vs int32: read first 64 entries as int64.
        // If the buffer is really int32 (e.g. arange), the reinterpreted
        // int64 values contain a nonzero high word -> out of [0, N).
        const long long* p64 = (const long long*)merge_idx;
        int ok = 1;
        int m = (int)(N < 64 ? N : 64);
        for (int i = 0; i < m; i++) {
            long long v = p64[i];
            if (v < 0 || v >= N) { ok = 0; break; }
        }
        g_idx64 = ok;
    }
}

// ---------------- kernel C: histogram of G ----------------
__global__ void k_count(const void* Gp, int total) {
    int is64 = g_idx64;
    int i = blockIdx.x * blockDim.x + threadIdx.x;
    if (i < total) {
        int g = (int)ld_idx(Gp, i, is64);
        atomicAdd(&g_cnt[g], 1.0f);
    }
}

// ---------------- kernel MW: M = U U^T,  W = U diag(cnt) U^T ----------------
// grid = nchunk*4 blocks, 256 threads. Each block: one 16-column chunk of U,
// one 64x64 quadrant of the 128x128 outputs. Thread = 4x4 micro-tile.
__global__ void k_mw(const float* __restrict__ U, int P) {
    __shared__ float sh[16][D_DIM];   // 8 KB: 16 columns of U (each a 128-vector)
    __shared__ float shc[16];

    int chunk = blockIdx.x >> 2;
    int quad  = blockIdx.x & 3;
    int p0 = chunk * 16;
    int tid = threadIdx.x;

    for (int e = tid; e < 16 * D_DIM; e += blockDim.x) {
        int d = e >> 4, pc = e & 15;
        int p = p0 + pc;
        sh[pc][d] = (p < P) ? U[(size_t)d * P + p] : 0.f;
    }
    if (tid < 16) {
        int p = p0 + tid;
        shc[tid] = (p < P) ? g_cnt[p] : 0.f;
    }
    __syncthreads();

    int ti = tid & 15, tj = tid >> 4;
    int i0 = (quad & 1) * 64 + ti * 4;
    int j0 = (quad >> 1) * 64 + tj * 4;

    float m[4][4] = {{0}}, w[4][4] = {{0}};
#pragma unroll
    for (int pc = 0; pc < 16; pc++) {
        float c = shc[pc];
        float a[4], ca[4], b[4];
#pragma unroll
        for (int x = 0; x < 4; x++) { a[x] = sh[pc][i0 + x]; ca[x] = c * a[x]; }
#pragma unroll
        for (int y = 0; y < 4; y++) b[y] = sh[pc][j0 + y];
#pragma unroll
        for (int x = 0; x < 4; x++)
#pragma unroll
            for (int y = 0; y < 4; y++) {
                m[x][y] += a[x] * b[y];
                w[x][y] += ca[x] * b[y];
            }
    }

#pragma unroll
    for (int x = 0; x < 4; x++)
#pragma unroll
        for (int y = 0; y < 4; y++) {
            int idx = (i0 + x) * D_DIM + (j0 + y);
            atomicAdd(&g_M[idx], m[x][y]);
            atomicAdd(&g_W[idx], w[x][y]);
        }
}

// ---------------- kernel D: the big HBM-bound dots pass ----------------
__global__ void __launch_bounds__(256)
k_dots(const float* __restrict__ Ub, const float* __restrict__ U,
       const void* midx, const void* segs,
       long long N, int P) {
    int is64 = g_idx64;
    long long j = (long long)blockIdx.x * blockDim.x + threadIdx.x;

    double val = 0.0;
    if (j < N) {
        long long mi = ld_idx(midx, j, is64);
        int g = (int)ld_idx(segs, j, is64);
        const float* ub = Ub + mi;
        const float* uu = U + g;
        float acc = 0.f;
#pragma unroll 8
        for (int d = 0; d < D_DIM; d++) {
            acc += __ldg(ub + (size_t)d * N) * __ldg(uu + (size_t)d * P);
        }
        val = (double)acc * (double)acc;
    }

    // block reduce (256 threads) in double
    __shared__ double red[8];
    unsigned mask = 0xFFFFFFFFu;
#pragma unroll
    for (int off = 16; off > 0; off >>= 1)
        val += __shfl_down_sync(mask, val, off);
    int lane = threadIdx.x & 31, warp = threadIdx.x >> 5;
    if (lane == 0) red[warp] = val;
    __syncthreads();
    if (warp == 0) {
        double s = (lane < 8) ? red[lane] : 0.0;
#pragma unroll
        for (int off = 4; off > 0; off >>= 1)
            s += __shfl_down_sync(mask, s, off);
        if (lane == 0) atomicAdd(&g_dots_acc, s);
    }
}

// ---------------- kernel F: trace(M .* W) + finalize ----------------
__global__ void k_final(float* out, double inv_den) {
    __shared__ double red[8];
    int tid = threadIdx.x;
    double s = 0.0;
    for (int i = tid; i < D_DIM * D_DIM; i += blockDim.x)
        s += (double)g_M[i] * (double)g_W[i];
    unsigned mask = 0xFFFFFFFFu;
#pragma unroll
    for (int off = 16; off > 0; off >>= 1)
        s += __shfl_down_sync(mask, s, off);
    int lane = tid & 31, warp = tid >> 5;
    if (lane == 0) red[warp] = s;
    __syncthreads();
    if (warp == 0) {
        double t = (lane < 8) ? red[lane] : 0.0;
#pragma unroll
        for (int off = 4; off > 0; off >>= 1)
            t += __shfl_down_sync(mask, t, off);
        if (lane == 0)
            out[0] = (float)(-0.5 * g_dots_acc - 0.5 * t * inv_den);
    }
}

// ---------------- launch ----------------
extern "C" void kernel_launch(void* const* d_in, const int* in_sizes, int n_in,
                              void* d_out, int out_size) {
    const float* U_base = (const float*)d_in[0];
    const float* U      = (const float*)d_in[1];
    const void*  midx   = d_in[2];
    const void*  segs   = d_in[3];
    const void*  Gp     = d_in[4];

    long long N = in_sizes[2];                 // merge_idx has N entries
    int D = (int)((long long)in_sizes[0] / N); // = 128
    int P = in_sizes[1] / D;                   // = 1024
    int PK = in_sizes[4];                      // P*K = 32768
    int K = PK / P;                            // = 32
    (void)D; (void)n_in;

    float* out = (float*)d_out;
    (void)out_size;

    // Z: zero scratch + dtype detect
    k_init<<<132, 256>>>(midx, N, P);

    // C: histogram of G
    k_count<<<(PK + 255) / 256, 256>>>(Gp, PK);

    // MW: dual weighted outer-product GEMM
    int nchunk = (P + 15) / 16;
    k_mw<<<nchunk * 4, 256>>>(U, P);

    // D: main HBM-bound pass
    long long nblk = (N + 255) / 256;
    k_dots<<<(unsigned)nblk, 256>>>(U_base, U, midx, segs, N, P);

    // F: finalize
    double inv_den = 1.0 / ((double)P * (double)K * (double)P);
    k_final<<<1, 256>>>(out, inv_den);
}